// round 3
// baseline (speedup 1.0000x reference)
#include <cuda_runtime.h>

#define CIN  512
#define COUT 256
#define BATCH 32
#define HIN  56
#define WIN  56
#define HO   28
#define WO   28
#define NPIX (HO*WO)          // 784
#define NTOT (BATCH*NPIX)     // 25088

#define TO  128   // output-channel tile
#define TPN 128   // flattened-pixel tile (25088/128 = 196 exact)
#define BK  16    // k chunk
#define WSS 132   // padded Ws row stride

// Scratch: pooled BN+ReLU activations, layout [Cin][B*784] fp32 (≈51.4 MB)
__device__ float g_hp[(size_t)CIN * NTOT];

// ---------- f32x2 packed-FMA helpers ----------
__device__ __forceinline__ unsigned long long pack2(float x, float y) {
    unsigned long long r;
    asm("mov.b64 %0, {%1, %2};" : "=l"(r) : "f"(x), "f"(y));
    return r;
}
__device__ __forceinline__ unsigned long long fma2(unsigned long long a,
                                                   unsigned long long b,
                                                   unsigned long long c) {
    unsigned long long d;
    asm("fma.rn.f32x2 %0, %1, %2, %3;" : "=l"(d) : "l"(a), "l"(b), "l"(c));
    return d;
}

// ---------- Kernel 1: BN + ReLU + 2x2 avgpool ----------
// One block per (c, b); 392 threads; each thread makes 2 output pixels
// from one float4 per input row. Writes hp[c][b*784 + p].
__global__ __launch_bounds__(392) void pool_bn_relu_kernel(
    const float* __restrict__ x,
    const float* __restrict__ bn_w, const float* __restrict__ bn_b,
    const float* __restrict__ r_mean, const float* __restrict__ r_var)
{
    const int c = blockIdx.x;
    const int b = blockIdx.y;
    const int tid = threadIdx.x;           // 0..391
    const int i  = tid / 14;               // output row 0..27
    const int jj = tid - i * 14;           // output col pair 0..13

    float s = bn_w[c] * rsqrtf(r_var[c] + 1e-5f);
    float t = fmaf(-r_mean[c], s, bn_b[c]);

    const float* xp = x + (((size_t)b * CIN + c) * HIN + 2 * i) * WIN + 4 * jj;
    float4 r0 = *(const float4*)xp;
    float4 r1 = *(const float4*)(xp + WIN);

    float o0 = fmaxf(fmaf(r0.x, s, t), 0.f) + fmaxf(fmaf(r0.y, s, t), 0.f)
             + fmaxf(fmaf(r1.x, s, t), 0.f) + fmaxf(fmaf(r1.y, s, t), 0.f);
    float o1 = fmaxf(fmaf(r0.z, s, t), 0.f) + fmaxf(fmaf(r0.w, s, t), 0.f)
             + fmaxf(fmaf(r1.z, s, t), 0.f) + fmaxf(fmaf(r1.w, s, t), 0.f);

    float2* dst = (float2*)&g_hp[(size_t)c * NTOT + (size_t)b * NPIX + i * WO + 2 * jj];
    *dst = make_float2(0.25f * o0, 0.25f * o1);
}

// ---------- Kernel 2: single flat GEMM  out = W[256,512] @ HP[512, 25088] ----------
// Block tile 128x128, 256 threads, 8x8 per thread (f32x2-pair accumulators).
__global__ __launch_bounds__(256, 2) void gemm_kernel(
    const float* __restrict__ wgt,   // [COUT, CIN]
    float* __restrict__ out)         // [B, COUT, 784]
{
    __shared__ float Ws[BK][WSS];    // transposed: Ws[k][o]
    __shared__ float Hs[BK][TPN];    // Hs[k][n]

    const int tid = threadIdx.x;
    const int tx  = tid & 15;        // n group (8 pixels each)
    const int ty  = tid >> 4;        // o group (8 channels each)
    const int n0  = blockIdx.x * TPN;
    const int o0  = blockIdx.y * TO;

    // global->shared load indexing
    const int wrow = tid >> 1;           // 0..127 (o within tile)
    const int wcol = (tid & 1) * 8;      // 0 or 8 (k offset)
    const int hrow = tid >> 4;           // 0..15  (k)
    const int hcol = (tid & 15) * 8;     // 0..120 (n offset)

    const float* wp = wgt + (size_t)(o0 + wrow) * CIN + wcol;
    const float* hp = g_hp + (size_t)hrow * NTOT + n0 + hcol;

    unsigned long long acc[8][4];
    #pragma unroll
    for (int r = 0; r < 8; r++)
        #pragma unroll
        for (int c = 0; c < 4; c++) acc[r][c] = 0ull;

    // prologue: prefetch k-tile 0
    float4 wv0 = *(const float4*)wp;
    float4 wv1 = *(const float4*)(wp + 4);
    float4 hv0 = *(const float4*)hp;
    float4 hv1 = *(const float4*)(hp + 4);

    for (int k0 = 0; k0 < CIN; k0 += BK) {
        // commit prefetched tile to smem
        Ws[wcol + 0][wrow] = wv0.x;
        Ws[wcol + 1][wrow] = wv0.y;
        Ws[wcol + 2][wrow] = wv0.z;
        Ws[wcol + 3][wrow] = wv0.w;
        Ws[wcol + 4][wrow] = wv1.x;
        Ws[wcol + 5][wrow] = wv1.y;
        Ws[wcol + 6][wrow] = wv1.z;
        Ws[wcol + 7][wrow] = wv1.w;
        *(float4*)&Hs[hrow][hcol]     = hv0;
        *(float4*)&Hs[hrow][hcol + 4] = hv1;

        __syncthreads();

        // prefetch next k-tile (latency hides under the FMA block)
        if (k0 + BK < CIN) {
            wp += BK; hp += (size_t)BK * NTOT;
            wv0 = *(const float4*)wp;
            wv1 = *(const float4*)(wp + 4);
            hv0 = *(const float4*)hp;
            hv1 = *(const float4*)(hp + 4);
        }

        #pragma unroll
        for (int kk = 0; kk < BK; kk++) {
            // W: 8 o-values (2-address broadcast across the warp)
            float4 w0 = *(const float4*)&Ws[kk][ty * 8];
            float4 w1 = *(const float4*)&Ws[kk][ty * 8 + 4];
            // H: 8 n-values, pre-packed as 4 f32x2 pairs
            ulonglong2 h01 = *(const ulonglong2*)&Hs[kk][tx * 8];
            ulonglong2 h23 = *(const ulonglong2*)&Hs[kk][tx * 8 + 4];

            unsigned long long a0 = pack2(w0.x, w0.x);
            unsigned long long a1 = pack2(w0.y, w0.y);
            unsigned long long a2 = pack2(w0.z, w0.z);
            unsigned long long a3 = pack2(w0.w, w0.w);
            unsigned long long a4 = pack2(w1.x, w1.x);
            unsigned long long a5 = pack2(w1.y, w1.y);
            unsigned long long a6 = pack2(w1.z, w1.z);
            unsigned long long a7 = pack2(w1.w, w1.w);

            acc[0][0] = fma2(a0, h01.x, acc[0][0]);
            acc[0][1] = fma2(a0, h01.y, acc[0][1]);
            acc[0][2] = fma2(a0, h23.x, acc[0][2]);
            acc[0][3] = fma2(a0, h23.y, acc[0][3]);
            acc[1][0] = fma2(a1, h01.x, acc[1][0]);
            acc[1][1] = fma2(a1, h01.y, acc[1][1]);
            acc[1][2] = fma2(a1, h23.x, acc[1][2]);
            acc[1][3] = fma2(a1, h23.y, acc[1][3]);
            acc[2][0] = fma2(a2, h01.x, acc[2][0]);
            acc[2][1] = fma2(a2, h01.y, acc[2][1]);
            acc[2][2] = fma2(a2, h23.x, acc[2][2]);
            acc[2][3] = fma2(a2, h23.y, acc[2][3]);
            acc[3][0] = fma2(a3, h01.x, acc[3][0]);
            acc[3][1] = fma2(a3, h01.y, acc[3][1]);
            acc[3][2] = fma2(a3, h23.x, acc[3][2]);
            acc[3][3] = fma2(a3, h23.y, acc[3][3]);
            acc[4][0] = fma2(a4, h01.x, acc[4][0]);
            acc[4][1] = fma2(a4, h01.y, acc[4][1]);
            acc[4][2] = fma2(a4, h23.x, acc[4][2]);
            acc[4][3] = fma2(a4, h23.y, acc[4][3]);
            acc[5][0] = fma2(a5, h01.x, acc[5][0]);
            acc[5][1] = fma2(a5, h01.y, acc[5][1]);
            acc[5][2] = fma2(a5, h23.x, acc[5][2]);
            acc[5][3] = fma2(a5, h23.y, acc[5][3]);
            acc[6][0] = fma2(a6, h01.x, acc[6][0]);
            acc[6][1] = fma2(a6, h01.y, acc[6][1]);
            acc[6][2] = fma2(a6, h23.x, acc[6][2]);
            acc[6][3] = fma2(a6, h23.y, acc[6][3]);
            acc[7][0] = fma2(a7, h01.x, acc[7][0]);
            acc[7][1] = fma2(a7, h01.y, acc[7][1]);
            acc[7][2] = fma2(a7, h23.x, acc[7][2]);
            acc[7][3] = fma2(a7, h23.y, acc[7][3]);
        }
        __syncthreads();
    }

    // store 8 o-rows x 8 n-cols per thread.
    // n span is 8-aligned and 784 % 8 == 0, so a thread's 8 columns never
    // cross an image boundary.
    const int nb = n0 + tx * 8;
    const int b  = nb / NPIX;
    const int p  = nb - b * NPIX;
    float* ob = out + ((size_t)b * COUT + o0 + ty * 8) * NPIX + p;
    #pragma unroll
    for (int r = 0; r < 8; r++) {
        ulonglong2 v0, v1;
        v0.x = acc[r][0]; v0.y = acc[r][1];
        v1.x = acc[r][2]; v1.y = acc[r][3];
        *(ulonglong2*)(ob + (size_t)r * NPIX)     = v0;
        *(ulonglong2*)(ob + (size_t)r * NPIX + 4) = v1;
    }
}

extern "C" void kernel_launch(void* const* d_in, const int* in_sizes, int n_in,
                              void* d_out, int out_size)
{
    const float* x    = (const float*)d_in[0];
    const float* bn_w = (const float*)d_in[1];
    const float* bn_b = (const float*)d_in[2];
    const float* rm   = (const float*)d_in[3];
    const float* rv   = (const float*)d_in[4];
    const float* wgt  = (const float*)d_in[5];
    float* out        = (float*)d_out;

    dim3 g1(CIN, BATCH);                 // (512, 32), 392 threads
    pool_bn_relu_kernel<<<g1, 392>>>(x, bn_w, bn_b, rm, rv);

    dim3 g2(NTOT / TPN, COUT / TO);      // (196, 2)
    gemm_kernel<<<g2, 256>>>(wgt, out);
}

// round 8
// speedup vs baseline: 1.1949x; 1.1949x over previous
#include <cuda_runtime.h>
#include <cstdint>

#define CIN  512
#define COUT 256
#define BATCH 32
#define HIN  56
#define WIN  56
#define HO   28
#define WO   28
#define NPIX (HO*WO)          // 784
#define NTOT (BATCH*NPIX)     // 25088

#define BM 64     // o tile per block
#define BN 128    // n tile per block
#define BK 16     // k chunk
#define WSP 20    // Ws row stride (floats): conflict-free A-frag LDS
#define HSP 136   // Hs row stride (floats): conflict-free B-frag LDS

// Scratch: pooled BN+ReLU activations, layout [Cin][B*784] fp32 (≈51.4 MB)
__device__ float g_hp[(size_t)CIN * NTOT];

// ---------- tf32 helpers ----------
__device__ __forceinline__ uint32_t f2tf32(float x) {
    uint32_t r;
    asm("cvt.rna.tf32.f32 %0, %1;" : "=r"(r) : "f"(x));
    return r;
}
// split x into hi (tf32) + lo (tf32 of remainder)
__device__ __forceinline__ void split_tf32(float x, uint32_t& hi, uint32_t& lo) {
    hi = f2tf32(x);
    float rem = x - __uint_as_float(hi);
    lo = f2tf32(rem);
}
__device__ __forceinline__ void mma_tf32(float& c0, float& c1, float& c2, float& c3,
                                         uint32_t a0, uint32_t a1, uint32_t a2, uint32_t a3,
                                         uint32_t b0, uint32_t b1) {
    asm volatile(
        "mma.sync.aligned.m16n8k8.row.col.f32.tf32.tf32.f32 "
        "{%0,%1,%2,%3}, {%4,%5,%6,%7}, {%8,%9}, {%0,%1,%2,%3};"
        : "+f"(c0), "+f"(c1), "+f"(c2), "+f"(c3)
        : "r"(a0), "r"(a1), "r"(a2), "r"(a3), "r"(b0), "r"(b1));
}

// ---------- Kernel 1: BN + ReLU + 2x2 avgpool ----------
__global__ __launch_bounds__(392) void pool_bn_relu_kernel(
    const float* __restrict__ x,
    const float* __restrict__ bn_w, const float* __restrict__ bn_b,
    const float* __restrict__ r_mean, const float* __restrict__ r_var)
{
    const int c = blockIdx.x;
    const int b = blockIdx.y;
    const int tid = threadIdx.x;           // 0..391
    const int i  = tid / 14;               // output row 0..27
    const int jj = tid - i * 14;           // output col pair 0..13

    float s = bn_w[c] * rsqrtf(r_var[c] + 1e-5f);
    float t = fmaf(-r_mean[c], s, bn_b[c]);

    const float* xp = x + (((size_t)b * CIN + c) * HIN + 2 * i) * WIN + 4 * jj;
    float4 r0 = *(const float4*)xp;
    float4 r1 = *(const float4*)(xp + WIN);

    float o0 = fmaxf(fmaf(r0.x, s, t), 0.f) + fmaxf(fmaf(r0.y, s, t), 0.f)
             + fmaxf(fmaf(r1.x, s, t), 0.f) + fmaxf(fmaf(r1.y, s, t), 0.f);
    float o1 = fmaxf(fmaf(r0.z, s, t), 0.f) + fmaxf(fmaf(r0.w, s, t), 0.f)
             + fmaxf(fmaf(r1.z, s, t), 0.f) + fmaxf(fmaf(r1.w, s, t), 0.f);

    float2* dst = (float2*)&g_hp[(size_t)c * NTOT + (size_t)b * NPIX + i * WO + 2 * jj];
    *dst = make_float2(0.25f * o0, 0.25f * o1);
}

// ---------- Kernel 2: 3xTF32 tensor-core GEMM  out = W[256,512] @ HP[512,25088] ----------
// 256 threads = 8 warps arranged 2(M) x 4(N); warp tile 32x32 = 2x4 m16n8k8 mmas.
__global__ __launch_bounds__(256, 2) void gemm_kernel(
    const float* __restrict__ wgt,   // [COUT, CIN]
    float* __restrict__ out)         // [B, COUT, 784]
{
    __shared__ float Ws[BM][WSP];    // Ws[o][k]
    __shared__ float Hs[BK][HSP];    // Hs[k][n]

    const int tid  = threadIdx.x;
    const int wid  = tid >> 5;
    const int lane = tid & 31;
    const int wm   = wid & 1;        // warp M index (0..1)
    const int wn   = wid >> 1;       // warp N index (0..3)
    const int q    = lane & 3;       // k quad
    const int r    = lane >> 2;      // row-in-frag 0..7

    const int n0 = blockIdx.x * BN;
    const int o0 = blockIdx.y * BM;

    // global->shared indexing
    const int wrow = tid >> 2;           // 0..63
    const int wcol = (tid & 3) * 4;      // 0,4,8,12
    const int hrow = tid >> 4;           // 0..15
    const int hcol = (tid & 15) * 8;     // 0..120

    const float* wp = wgt + (size_t)(o0 + wrow) * CIN + wcol;
    const float* hp = g_hp + (size_t)hrow * NTOT + n0 + hcol;

    float acc[2][4][4];
    #pragma unroll
    for (int mi = 0; mi < 2; mi++)
        #pragma unroll
        for (int ni = 0; ni < 4; ni++)
            #pragma unroll
            for (int e = 0; e < 4; e++) acc[mi][ni][e] = 0.f;

    // prologue prefetch
    float4 wv = *(const float4*)wp;
    float4 hv0 = *(const float4*)hp;
    float4 hv1 = *(const float4*)(hp + 4);

    for (int k0 = 0; k0 < CIN; k0 += BK) {
        *(float4*)&Ws[wrow][wcol] = wv;
        *(float4*)&Hs[hrow][hcol]     = hv0;
        *(float4*)&Hs[hrow][hcol + 4] = hv1;
        __syncthreads();

        if (k0 + BK < CIN) {
            wp += BK; hp += (size_t)BK * NTOT;
            wv  = *(const float4*)wp;
            hv0 = *(const float4*)hp;
            hv1 = *(const float4*)(hp + 4);
        }

        #pragma unroll
        for (int kk = 0; kk < BK; kk += 8) {
            // ---- load + split A fragments (W) ----
            uint32_t ah[2][4], al[2][4];
            #pragma unroll
            for (int mi = 0; mi < 2; mi++) {
                int row = wm * 32 + mi * 16 + r;
                float a0 = Ws[row][kk + q];
                float a1 = Ws[row + 8][kk + q];
                float a2 = Ws[row][kk + q + 4];
                float a3 = Ws[row + 8][kk + q + 4];
                split_tf32(a0, ah[mi][0], al[mi][0]);
                split_tf32(a1, ah[mi][1], al[mi][1]);
                split_tf32(a2, ah[mi][2], al[mi][2]);
                split_tf32(a3, ah[mi][3], al[mi][3]);
            }
            // ---- load + split B fragments (H) ----
            uint32_t bh[4][2], bl[4][2];
            #pragma unroll
            for (int ni = 0; ni < 4; ni++) {
                int col = wn * 32 + ni * 8 + r;
                float b0 = Hs[kk + q][col];
                float b1 = Hs[kk + q + 4][col];
                split_tf32(b0, bh[ni][0], bl[ni][0]);
                split_tf32(b1, bh[ni][1], bl[ni][1]);
            }
            // ---- 3xTF32 mma: hi*hi + hi*lo + lo*hi ----
            #pragma unroll
            for (int mi = 0; mi < 2; mi++)
                #pragma unroll
                for (int ni = 0; ni < 4; ni++) {
                    float* c = acc[mi][ni];
                    mma_tf32(c[0], c[1], c[2], c[3],
                             ah[mi][0], ah[mi][1], ah[mi][2], ah[mi][3],
                             bh[ni][0], bh[ni][1]);
                    mma_tf32(c[0], c[1], c[2], c[3],
                             ah[mi][0], ah[mi][1], ah[mi][2], ah[mi][3],
                             bl[ni][0], bl[ni][1]);
                    mma_tf32(c[0], c[1], c[2], c[3],
                             al[mi][0], al[mi][1], al[mi][2], al[mi][3],
                             bh[ni][0], bh[ni][1]);
                }
        }
        __syncthreads();
    }

    // ---- epilogue: c0,c1 -> (row, col 2q, 2q+1); c2,c3 -> row+8 ----
    #pragma unroll
    for (int mi = 0; mi < 2; mi++) {
        int orow = o0 + wm * 32 + mi * 16 + r;
        #pragma unroll
        for (int ni = 0; ni < 4; ni++) {
            int n = n0 + wn * 32 + ni * 8 + 2 * q;
            int bimg = n / NPIX;
            int p = n - bimg * NPIX;
            float* ob = out + ((size_t)bimg * COUT + orow) * NPIX + p;
            *(float2*)ob = make_float2(acc[mi][ni][0], acc[mi][ni][1]);
            *(float2*)(ob + 8 * NPIX) = make_float2(acc[mi][ni][2], acc[mi][ni][3]);
        }
    }
}

extern "C" void kernel_launch(void* const* d_in, const int* in_sizes, int n_in,
                              void* d_out, int out_size)
{
    const float* x    = (const float*)d_in[0];
    const float* bn_w = (const float*)d_in[1];
    const float* bn_b = (const float*)d_in[2];
    const float* rm   = (const float*)d_in[3];
    const float* rv   = (const float*)d_in[4];
    const float* wgt  = (const float*)d_in[5];
    float* out        = (float*)d_out;

    dim3 g1(CIN, BATCH);                 // (512, 32), 392 threads
    pool_bn_relu_kernel<<<g1, 392>>>(x, bn_w, bn_b, rm, rv);

    dim3 g2(NTOT / BN, COUT / BM);       // (196, 4)
    gemm_kernel<<<g2, 256>>>(wgt, out);
}